// round 5
// baseline (speedup 1.0000x reference)
#include <cuda_runtime.h>
#include <cuda_bf16.h>

// Problem constants
#define BATCH   512
#define T_STEPS 8
#define DIM     512
#define HID     512
#define LATD    64
#define NSTEPS  4
// derived
#define OUT_O   (BATCH * 2 * LATD)      // 65536
#define OUT_H   (BATCH * HID)           // 262144

// ---------------- scratch (device globals: no allocation allowed) ----------
__device__ float g_h  [BATCH * HID];
__device__ float g_k  [BATCH * HID];
__device__ float g_acc[BATCH * HID];
__device__ float g_z1 [BATCH * 1024];
__device__ float g_z2 [BATCH * 1024];
__device__ float g_gi [BATCH * 1536];
__device__ float g_gh [BATCH * 1536];

// ---------------- GEMM config ----------------
// C(MxN) = epi( A(MxK) @ W(NxK)^T + bias )
// Both A and W are K-contiguous ("NT" layout) -> coalesced loads along K.
constexpr int BM = 32, BN = 64, BK = 32;
constexpr int TM = 4,  TN = 4;
constexpr int NT = (BM / TM) * (BN / TN);   // 128 threads
constexpr int SAS = BM + 4;                 // padded strides (keep float4 align, reduce conflicts)
constexpr int SWS = BN + 4;

struct GP {
    const float* A;  int lda;
    const float* W;  int ldw;
    const float* bias;
    float* C;
    int M, N, K;
    // AMODE 1 (virtual A = [h + amul*dt*k | t0 + tc*dt]):
    const float* hbuf; const float* kbuf; const float* ts;
    float amul, tc; int step;
    // EPI 2 (RK4 k accumulation):
    float* acc; float* hout; float kw; int first, last;
};

__device__ __forceinline__ float sigm(float x) { return 1.f / (1.f + __expf(-x)); }

// AMODE: 0 = plain A pointer, 1 = ODE virtual A
// EPI:   0 = bias only, 1 = bias + swish, 2 = RK4 k-epilogue
template<int AMODE, int EPI>
__global__ __launch_bounds__(NT) void gemm_k(GP p) {
    __shared__ __align__(16) float sA[BK * SAS];
    __shared__ __align__(16) float sW[BK * SWS];

    const int tid   = threadIdx.x;
    const int mBase = blockIdx.y * BM;
    const int nBase = blockIdx.x * BN;
    const int tm    = tid & 7;    // 0..7  -> rows tm*4..tm*4+3
    const int tn    = tid >> 3;   // 0..15 -> cols tn*4..tn*4+3

    float accr[TM][TN];
#pragma unroll
    for (int i = 0; i < TM; i++)
#pragma unroll
        for (int j = 0; j < TN; j++) accr[i][j] = 0.f;

    const int KT = (p.K + BK - 1) / BK;
    for (int kt = 0; kt < KT; kt++) {
        const int k0 = kt * BK;
        // ---- load A tile (coalesced along K; scalar with guards) ----
#pragma unroll
        for (int l = tid; l < BM * BK; l += NT) {
            const int kk = l & 31, m = l >> 5;
            const int kcol = k0 + kk;
            const int grow = mBase + m;
            float v = 0.f;
            if (kcol < p.K) {
                if (AMODE == 0) {
                    v = p.A[grow * p.lda + kcol];
                } else {
                    if (kcol < p.K - 1) {
                        v = p.hbuf[grow * HID + kcol];
                        if (p.amul != 0.f) {
                            const float tpr = p.ts[grow * T_STEPS + p.step - 1];
                            const float tcu = p.ts[grow * T_STEPS + p.step];
                            const float dt  = (tcu - tpr) * 0.25f;
                            v += p.amul * dt * p.kbuf[grow * HID + kcol];
                        }
                    } else {  // time column
                        const float tpr = p.ts[grow * T_STEPS + p.step - 1];
                        const float tcu = p.ts[grow * T_STEPS + p.step];
                        const float dt  = (tcu - tpr) * 0.25f;
                        v = tpr + p.tc * dt;
                    }
                }
            }
            sA[kk * SAS + m] = v;
        }
        // ---- load W tile (coalesced along K) ----
#pragma unroll
        for (int l = tid; l < BN * BK; l += NT) {
            const int kk = l & 31, n = l >> 5;
            const int kcol = k0 + kk;
            const int col  = nBase + n;
            float v = 0.f;
            if (kcol < p.K) v = p.W[col * p.ldw + kcol];
            sW[kk * SWS + n] = v;
        }
        __syncthreads();
        // ---- compute: float4 LDS (broadcast, conflict-free), 16 FFMA/k ----
#pragma unroll
        for (int kk = 0; kk < BK; kk++) {
            const float4 a = *(const float4*)&sA[kk * SAS + tm * 4];
            const float4 w = *(const float4*)&sW[kk * SWS + tn * 4];
            const float av[4] = {a.x, a.y, a.z, a.w};
            const float wv[4] = {w.x, w.y, w.z, w.w};
#pragma unroll
            for (int i = 0; i < TM; i++)
#pragma unroll
                for (int j = 0; j < TN; j++)
                    accr[i][j] += av[i] * wv[j];
        }
        __syncthreads();
    }

    // ---- epilogue ----
#pragma unroll
    for (int i = 0; i < TM; i++) {
        const int r = mBase + tm * 4 + i;
#pragma unroll
        for (int j = 0; j < TN; j++) {
            const int c = nBase + tn * 4 + j;
            float v = accr[i][j] + p.bias[c];
            if (EPI == 1) v = v * sigm(v);             // swish
            if (EPI == 0 || EPI == 1) {
                p.C[r * p.N + c] = v;
            } else {                                    // EPI == 2: RK4 k handling
                const int idx = r * p.N + c;
                if (!p.last) {
                    p.C[idx]   = v;                     // k needed by next eval
                    p.acc[idx] = p.first ? v : p.acc[idx] + p.kw * v;
                } else {                                // h += dt/6 * (k1+2k2+2k3+k4)
                    const float tpr = p.ts[r * T_STEPS + p.step - 1];
                    const float tcu = p.ts[r * T_STEPS + p.step];
                    const float dt  = (tcu - tpr) * 0.25f;
                    p.hout[idx] += dt * (1.f / 6.f) * (p.acc[idx] + v);
                }
            }
        }
    }
}

// ---------------- elementwise kernels ----------------
__global__ void zero_kernel(float* p, int n) {
    int i = blockIdx.x * blockDim.x + threadIdx.x;
    if (i < n) p[i] = 0.f;
}

__global__ void gru_gate_kernel(const float* __restrict__ gi,
                                const float* __restrict__ gh,
                                float* __restrict__ h) {
    int idx = blockIdx.x * blockDim.x + threadIdx.x;
    if (idx >= BATCH * HID) return;
    const int i = idx >> 9, j = idx & 511;
    const float* gir = gi + i * 1536;
    const float* ghr = gh + i * 1536;
    const float r  = sigm(gir[j]        + ghr[j]);
    const float z  = sigm(gir[512 + j]  + ghr[512 + j]);
    const float n  = tanhf(gir[1024 + j] + r * ghr[1024 + j]);
    const float ho = h[idx];
    h[idx] = (1.f - z) * n + z * ho;
}

__global__ void finalize_kernel(const float* __restrict__ h, float* __restrict__ out) {
    int i = blockIdx.x * blockDim.x + threadIdx.x;
    if (i < BATCH * HID) {
        out[OUT_O + i]         = h[i];   // h
        out[OUT_O + OUT_H + i] = 0.f;    // c (never updated -> zeros)
    }
}

// ---------------- launch sequence ----------------
static inline dim3 grid_for(int M, int N) { return dim3(N / BN, M / BM); }

extern "C" void kernel_launch(void* const* d_in, const int* in_sizes, int n_in,
                              void* d_out, int out_size) {
    const float* x    = (const float*)d_in[0];
    const float* ts   = (const float*)d_in[1];
    const float* Wih  = (const float*)d_in[2];
    const float* Whh  = (const float*)d_in[3];
    const float* bih  = (const float*)d_in[4];
    const float* bhh  = (const float*)d_in[5];
    const float* Wout = (const float*)d_in[6];
    const float* bout = (const float*)d_in[7];
    const float* W1   = (const float*)d_in[8];
    const float* b1   = (const float*)d_in[9];
    const float* W2   = (const float*)d_in[10];
    const float* b2   = (const float*)d_in[11];
    const float* W3   = (const float*)d_in[12];
    const float* b3   = (const float*)d_in[13];
    float* out = (float*)d_out;

    float *h, *k, *acc, *z1, *z2, *gi, *gh;
    cudaGetSymbolAddress((void**)&h,   g_h);
    cudaGetSymbolAddress((void**)&k,   g_k);
    cudaGetSymbolAddress((void**)&acc, g_acc);
    cudaGetSymbolAddress((void**)&z1,  g_z1);
    cudaGetSymbolAddress((void**)&z2,  g_z2);
    cudaGetSymbolAddress((void**)&gi,  g_gi);
    cudaGetSymbolAddress((void**)&gh,  g_gh);

    zero_kernel<<<(BATCH * HID + 255) / 256, 256>>>(h, BATCH * HID);

    const float amuls[4] = {0.f, 0.5f, 0.5f, 1.f};
    const float tcs  [4] = {0.f, 0.5f, 0.5f, 1.f};
    const float kws  [4] = {0.f, 2.f, 2.f, 1.f};

    for (int step = 0; step < T_STEPS; step++) {
        // Step 0: t_prev == ts[:,0] -> dt = 0 -> ODE update is exactly identity. Skip.
        if (step > 0) {
            for (int rk = 0; rk < NSTEPS; rk++) {
                for (int ev = 0; ev < 4; ev++) {
                    // z1 = swish([h + amul*dt*k | t0 + tc*dt] @ W1^T + b1)
                    GP p1 = {};
                    p1.W = W1; p1.ldw = DIM + 1; p1.bias = b1; p1.C = z1;
                    p1.M = BATCH; p1.N = 1024; p1.K = DIM + 1;
                    p1.hbuf = h; p1.kbuf = (ev == 0 ? h : k); p1.ts = ts;
                    p1.amul = amuls[ev]; p1.tc = (float)rk + tcs[ev]; p1.step = step;
                    gemm_k<1, 1><<<grid_for(BATCH, 1024), NT>>>(p1);

                    // z2 = swish(z1 @ W2^T + b2)
                    GP p2 = {};
                    p2.A = z1; p2.lda = 1024; p2.W = W2; p2.ldw = 1024; p2.bias = b2;
                    p2.C = z2; p2.M = BATCH; p2.N = 1024; p2.K = 1024;
                    gemm_k<0, 1><<<grid_for(BATCH, 1024), NT>>>(p2);

                    // k_ev = z2 @ W3^T + b3 ; fused RK4 accumulation / h update
                    GP p3 = {};
                    p3.A = z2; p3.lda = 1024; p3.W = W3; p3.ldw = 1024; p3.bias = b3;
                    p3.C = k; p3.M = BATCH; p3.N = HID; p3.K = 1024;
                    p3.acc = acc; p3.hout = h; p3.kw = kws[ev];
                    p3.first = (ev == 0); p3.last = (ev == 3);
                    p3.ts = ts; p3.step = step;
                    gemm_k<0, 2><<<grid_for(BATCH, HID), NT>>>(p3);
                }
            }
        }
        // GRU cell
        GP pg1 = {};
        pg1.A = x + step * DIM; pg1.lda = T_STEPS * DIM;
        pg1.W = Wih; pg1.ldw = DIM; pg1.bias = bih; pg1.C = gi;
        pg1.M = BATCH; pg1.N = 1536; pg1.K = DIM;
        gemm_k<0, 0><<<grid_for(BATCH, 1536), NT>>>(pg1);

        GP pg2 = {};
        pg2.A = h; pg2.lda = HID;
        pg2.W = Whh; pg2.ldw = HID; pg2.bias = bhh; pg2.C = gh;
        pg2.M = BATCH; pg2.N = 1536; pg2.K = HID;
        gemm_k<0, 0><<<grid_for(BATCH, 1536), NT>>>(pg2);

        gru_gate_kernel<<<(BATCH * HID + 255) / 256, 256>>>(gi, gh, h);
    }

    // Only outs[-1] is returned: one Wout GEMM at the end.
    GP po = {};
    po.A = h; po.lda = HID; po.W = Wout; po.ldw = HID; po.bias = bout;
    po.C = out; po.M = BATCH; po.N = 2 * LATD; po.K = HID;
    gemm_k<0, 0><<<grid_for(BATCH, 2 * LATD), NT>>>(po);

    finalize_kernel<<<(BATCH * HID + 255) / 256, 256>>>(h, out);
}

// round 8
// speedup vs baseline: 2.1386x; 2.1386x over previous
#include <cuda_runtime.h>
#include <cuda_bf16.h>
#include <cstdint>

#define BATCH   512
#define T_STEPS 8
#define HID     512
#define LATD    64
#define NSTEPS  4
#define OUT_O   (BATCH * 2 * LATD)
#define OUT_H   (BATCH * HID)
#define K1P     576               // 513 padded to multiple of 64
#define LDA1    (3 * K1P)         // 1728: [hi | hi | lo]
#define LDZ     3072              // z buffers: [hi(1024) | hi(1024) | lo(1024)]
#define LDX     1536              // x: [hi(512) | hi(512) | lo(512)]

// ---------------- scratch (device globals) ----------------
__device__ float g_h  [BATCH * HID];
__device__ float g_acc[BATCH * HID];
__device__ float g_gi [BATCH * 1536];
__device__ float g_gh [BATCH * 1536];
__device__ __nv_bfloat16 g_A1  [BATCH * LDA1];
__device__ __nv_bfloat16 g_z1b [BATCH * LDZ];
__device__ __nv_bfloat16 g_z2b [BATCH * LDZ];
__device__ __nv_bfloat16 g_xb  [T_STEPS * BATCH * LDX];
__device__ __nv_bfloat16 g_W1b [1024 * LDA1];
__device__ __nv_bfloat16 g_W2b [1024 * LDZ];
__device__ __nv_bfloat16 g_W3b [512 * LDZ];
__device__ __nv_bfloat16 g_Wihb[1536 * LDX];
__device__ __nv_bfloat16 g_Whhb[1536 * LDA1];
__device__ __nv_bfloat16 g_Woutb[128 * LDA1];

// ---------------- helpers ----------------
__device__ __forceinline__ uint32_t smem_u32(const void* p) {
    uint32_t a;
    asm("{ .reg .u64 t; cvta.to.shared.u64 t, %1; cvt.u32.u64 %0, t; }" : "=r"(a) : "l"(p));
    return a;
}
template<int N> __device__ __forceinline__ void cp_wait() {
    asm volatile("cp.async.wait_group %0;" :: "n"(N) : "memory");
}
__device__ __forceinline__ float sigm(float x) { return 1.f / (1.f + __expf(-x)); }
__device__ __forceinline__ __nv_bfloat162 pk2(__nv_bfloat16 a, __nv_bfloat16 b) {
    __nv_bfloat162 t; t.x = a; t.y = b; return t;
}

// ---------------- GEMM: C(512xN) = epi(A(512xK) @ W(NxK)^T + bias) ----------
// A rows: [hi|hi|lo] bf16, W rows: [hi|lo|hi] bf16 -> dot = hi*hi + hi*lo + lo*hi.
constexpr int SROW = 40;   // smem row stride (bf16): conflict-free ldmatrix phases

struct GemmP {
    const __nv_bfloat16* A;
    const __nv_bfloat16* W;
    const float* bias;
    int K;
    // EPI 0: f32 out
    float* Cf; int ldc;
    // EPI 1: bias+swish -> bf16 [hi|hi|lo]
    __nv_bfloat16* Cb; int ldcb; int seg;
    // EPI 2: RK4
    const float* ts; int step;
    float kw, amul_next, tc_next; int first, last;
    float* acc; float* h; __nv_bfloat16* A1;
};

// EPI: 0 = bias->f32, 1 = bias+swish->bf16 split, 2 = RK4 epilogue
template<int EPI>
__global__ __launch_bounds__(128) void gemm_mma(GemmP p) {
    __shared__ __align__(16) __nv_bfloat16 sA[3][64 * SROW];
    __shared__ __align__(16) __nv_bfloat16 sB[3][64 * SROW];
    const int tid  = threadIdx.x;
    const int lane = tid & 31, wid = tid >> 5;
    const int wm = wid >> 1, wn = wid & 1;          // 2x2 warp grid, 32x32 per warp
    const int mBase = blockIdx.y * 64;
    const int nBase = blockIdx.x * 64;
    const int KT = p.K >> 5;

    float ac[2][4][4];
#pragma unroll
    for (int i = 0; i < 2; i++)
#pragma unroll
        for (int j = 0; j < 4; j++)
#pragma unroll
            for (int q = 0; q < 4; q++) ac[i][j][q] = 0.f;

    const int lr = tid >> 2;          // 0..31
    const int lc = (tid & 3) * 8;     // 0,8,16,24

    auto load_stage = [&](int s, int kt) {
        const __nv_bfloat16* Ag = p.A + (size_t)mBase * p.K + kt * 32;
        const __nv_bfloat16* Wg = p.W + (size_t)nBase * p.K + kt * 32;
        const uint32_t a0 = smem_u32(&sA[s][0]);
        const uint32_t b0 = smem_u32(&sB[s][0]);
#pragma unroll
        for (int hh = 0; hh < 2; hh++) {
            const int r = lr + hh * 32;
            const uint32_t da = a0 + (uint32_t)(r * SROW + lc) * 2;
            const void* srca = (const void*)(Ag + (size_t)r * p.K + lc);
            asm volatile("cp.async.cg.shared.global [%0], [%1], 16;" :: "r"(da), "l"(srca) : "memory");
            const uint32_t db = b0 + (uint32_t)(r * SROW + lc) * 2;
            const void* srcb = (const void*)(Wg + (size_t)r * p.K + lc);
            asm volatile("cp.async.cg.shared.global [%0], [%1], 16;" :: "r"(db), "l"(srcb) : "memory");
        }
        asm volatile("cp.async.commit_group;" ::: "memory");
    };

    auto compute = [&](int s) {
        const uint32_t aB = smem_u32(&sA[s][0]);
        const uint32_t bB = smem_u32(&sB[s][0]);
#pragma unroll
        for (int kk = 0; kk < 32; kk += 16) {
            uint32_t af[2][4], bf[4][2];
#pragma unroll
            for (int i = 0; i < 2; i++) {
                const uint32_t ad = aB +
                    (uint32_t)(((wm * 32 + i * 16 + (lane & 15)) * SROW + kk + (lane >> 4) * 8) * 2);
                asm volatile("ldmatrix.sync.aligned.m8n8.x4.shared.b16 {%0,%1,%2,%3}, [%4];"
                    : "=r"(af[i][0]), "=r"(af[i][1]), "=r"(af[i][2]), "=r"(af[i][3]) : "r"(ad));
            }
#pragma unroll
            for (int jp = 0; jp < 2; jp++) {
                const int n = wn * 32 + jp * 16 + (lane >> 4) * 8 + (lane & 7);
                const int c = kk + ((lane >> 3) & 1) * 8;
                const uint32_t bd = bB + (uint32_t)((n * SROW + c) * 2);
                uint32_t r0, r1, r2, r3;
                asm volatile("ldmatrix.sync.aligned.m8n8.x4.shared.b16 {%0,%1,%2,%3}, [%4];"
                    : "=r"(r0), "=r"(r1), "=r"(r2), "=r"(r3) : "r"(bd));
                bf[jp * 2][0] = r0; bf[jp * 2][1] = r1;
                bf[jp * 2 + 1][0] = r2; bf[jp * 2 + 1][1] = r3;
            }
#pragma unroll
            for (int i = 0; i < 2; i++)
#pragma unroll
                for (int j = 0; j < 4; j++)
                    asm volatile(
                        "mma.sync.aligned.m16n8k16.row.col.f32.bf16.bf16.f32 "
                        "{%0,%1,%2,%3}, {%4,%5,%6,%7}, {%8,%9}, {%0,%1,%2,%3};"
                        : "+f"(ac[i][j][0]), "+f"(ac[i][j][1]), "+f"(ac[i][j][2]), "+f"(ac[i][j][3])
                        : "r"(af[i][0]), "r"(af[i][1]), "r"(af[i][2]), "r"(af[i][3]),
                          "r"(bf[j][0]), "r"(bf[j][1]));
        }
    };

    load_stage(0, 0);
    if (KT > 1) load_stage(1, 1);
    for (int kt = 0; kt < KT; kt++) {
        if (kt == KT - 1) cp_wait<0>(); else cp_wait<1>();
        __syncthreads();
        if (kt + 2 < KT) load_stage((kt + 2) % 3, kt + 2);
        compute(kt % 3);
    }

    // ---- epilogue ----
    const int rb = mBase + wm * 32 + (lane >> 2);
    const int cb = nBase + wn * 32 + (lane & 3) * 2;
#pragma unroll
    for (int i = 0; i < 2; i++) {
#pragma unroll
        for (int rh = 0; rh < 2; rh++) {
            const int r = rb + i * 16 + rh * 8;
            float tpr = 0.f, dt = 0.f;
            if (EPI == 2) {
                tpr = p.ts[r * T_STEPS + p.step - 1];
                const float tcu = p.ts[r * T_STEPS + p.step];
                dt = (tcu - tpr) * 0.25f;
            }
#pragma unroll
            for (int j = 0; j < 4; j++) {
                const int c = cb + j * 8;
                float v0 = ac[i][j][rh * 2 + 0] + p.bias[c];
                float v1 = ac[i][j][rh * 2 + 1] + p.bias[c + 1];
                if (EPI == 0) {
                    float2 st = {v0, v1};
                    *(float2*)(p.Cf + (size_t)r * p.ldc + c) = st;
                } else if (EPI == 1) {
                    v0 = v0 * sigm(v0);
                    v1 = v1 * sigm(v1);
                    const __nv_bfloat16 h0 = __float2bfloat16_rn(v0);
                    const __nv_bfloat16 h1 = __float2bfloat16_rn(v1);
                    const __nv_bfloat162 hp = pk2(h0, h1);
                    const __nv_bfloat162 lp =
                        pk2(__float2bfloat16_rn(v0 - __bfloat162float(h0)),
                            __float2bfloat16_rn(v1 - __bfloat162float(h1)));
                    __nv_bfloat16* Ch = p.Cb + (size_t)r * p.ldcb + c;
                    *(__nv_bfloat162*)Ch               = hp;
                    *(__nv_bfloat162*)(Ch + p.seg)     = hp;
                    *(__nv_bfloat162*)(Ch + 2 * p.seg) = lp;
                } else {  // EPI == 2
                    const size_t idx = (size_t)r * HID + c;
                    float a0, a1v;
                    if (!p.last) {
                        const float av0 = p.first ? v0 : p.acc[idx]     + p.kw * v0;
                        const float av1 = p.first ? v1 : p.acc[idx + 1] + p.kw * v1;
                        p.acc[idx] = av0; p.acc[idx + 1] = av1;
                        a0  = p.h[idx]     + p.amul_next * dt * v0;
                        a1v = p.h[idx + 1] + p.amul_next * dt * v1;
                    } else {
                        a0  = p.h[idx]     + dt * (1.f / 6.f) * (p.acc[idx]     + v0);
                        a1v = p.h[idx + 1] + dt * (1.f / 6.f) * (p.acc[idx + 1] + v1);
                        p.h[idx] = a0; p.h[idx + 1] = a1v;
                    }
                    const __nv_bfloat16 h0 = __float2bfloat16_rn(a0);
                    const __nv_bfloat16 h1 = __float2bfloat16_rn(a1v);
                    const __nv_bfloat162 hp = pk2(h0, h1);
                    const __nv_bfloat162 lp =
                        pk2(__float2bfloat16_rn(a0 - __bfloat162float(h0)),
                            __float2bfloat16_rn(a1v - __bfloat162float(h1)));
                    __nv_bfloat16* Ah = p.A1 + (size_t)r * LDA1 + c;
                    *(__nv_bfloat162*)Ah             = hp;
                    *(__nv_bfloat162*)(Ah + K1P)     = hp;
                    *(__nv_bfloat162*)(Ah + 2 * K1P) = lp;
                }
            }
            if (EPI == 2 && nBase == 0 && wn == 0 && (lane & 3) == 0) {
                const float tn = tpr + p.tc_next * dt;
                const __nv_bfloat16 th = __float2bfloat16_rn(tn);
                const __nv_bfloat16 tl = __float2bfloat16_rn(tn - __bfloat162float(th));
                p.A1[(size_t)r * LDA1 + HID]           = th;
                p.A1[(size_t)r * LDA1 + K1P + HID]     = th;
                p.A1[(size_t)r * LDA1 + 2 * K1P + HID] = tl;
            }
        }
    }
}

// ---------------- elementwise / setup kernels ----------------
__global__ void zero_f(float* p, int n) {
    int i = blockIdx.x * blockDim.x + threadIdx.x;
    if (i < n) p[i] = 0.f;
}
__global__ void zero_bf(__nv_bfloat16* p, int n) {
    int i = blockIdx.x * blockDim.x + threadIdx.x;
    if (i < n) p[i] = __float2bfloat16_rn(0.f);
}
// W[N][K] -> Wb[N][3*Kp] = [hi | lo | hi], zero-padded cols K..Kp-1
__global__ void conv_w(const float* __restrict__ W, __nv_bfloat16* __restrict__ Wb,
                       int N, int K, int Kp) {
    int idx = blockIdx.x * blockDim.x + threadIdx.x;
    if (idx >= N * Kp) return;
    const int n = idx / Kp, c = idx - n * Kp;
    const float v = (c < K) ? W[(size_t)n * K + c] : 0.f;
    const __nv_bfloat16 hi = __float2bfloat16_rn(v);
    const __nv_bfloat16 lo = __float2bfloat16_rn(v - __bfloat162float(hi));
    Wb[(size_t)n * 3 * Kp + c]          = hi;
    Wb[(size_t)n * 3 * Kp + Kp + c]     = lo;
    Wb[(size_t)n * 3 * Kp + 2 * Kp + c] = hi;
}
// x -> xb[step][r][1536] = [hi(512) | hi(512) | lo(512)]  (A-side layout)
__global__ void conv_x(const float* __restrict__ x, __nv_bfloat16* __restrict__ xb) {
    int idx = blockIdx.x * blockDim.x + threadIdx.x;   // idx = r*4096 + s*512 + c
    if (idx >= BATCH * T_STEPS * 512) return;
    const int c = idx & 511, s = (idx >> 9) & 7, r = idx >> 12;
    const float v = x[idx];
    const __nv_bfloat16 hi = __float2bfloat16_rn(v);
    __nv_bfloat16* dst = xb + ((size_t)s * BATCH + r) * LDX;
    dst[c]        = hi;
    dst[512 + c]  = hi;
    dst[1024 + c] = __float2bfloat16_rn(v - __bfloat162float(hi));
}
__global__ void gru_gate(const float* __restrict__ gi, const float* __restrict__ gh,
                         float* __restrict__ h, __nv_bfloat16* __restrict__ A1,
                         const float* __restrict__ ts, int step) {
    int idx = blockIdx.x * blockDim.x + threadIdx.x;
    if (idx >= BATCH * HID) return;
    const int r = idx >> 9, j = idx & 511;
    const float* gir = gi + (size_t)r * 1536;
    const float* ghr = gh + (size_t)r * 1536;
    const float rr = sigm(gir[j] + ghr[j]);
    const float zz = sigm(gir[512 + j] + ghr[512 + j]);
    const float nn = tanhf(gir[1024 + j] + rr * ghr[1024 + j]);
    const float hn = (1.f - zz) * nn + zz * h[idx];
    h[idx] = hn;
    const __nv_bfloat16 hi = __float2bfloat16_rn(hn);
    const __nv_bfloat16 lo = __float2bfloat16_rn(hn - __bfloat162float(hi));
    A1[(size_t)r * LDA1 + j]           = hi;
    A1[(size_t)r * LDA1 + K1P + j]     = hi;
    A1[(size_t)r * LDA1 + 2 * K1P + j] = lo;
    if (j == 0) {  // time column for next step: t_prev = ts[:, step]
        const float t = ts[r * T_STEPS + step];
        const __nv_bfloat16 th = __float2bfloat16_rn(t);
        const __nv_bfloat16 tl = __float2bfloat16_rn(t - __bfloat162float(th));
        A1[(size_t)r * LDA1 + HID]           = th;
        A1[(size_t)r * LDA1 + K1P + HID]     = th;
        A1[(size_t)r * LDA1 + 2 * K1P + HID] = tl;
    }
}
__global__ void finalize_k(const float* __restrict__ h, float* __restrict__ out) {
    int i = blockIdx.x * blockDim.x + threadIdx.x;
    if (i < BATCH * HID) {
        out[OUT_O + i]         = h[i];
        out[OUT_O + OUT_H + i] = 0.f;   // c never updated -> zeros
    }
}

// ---------------- host ----------------
extern "C" void kernel_launch(void* const* d_in, const int* in_sizes, int n_in,
                              void* d_out, int out_size) {
    const float* x    = (const float*)d_in[0];
    const float* ts   = (const float*)d_in[1];
    const float* Wih  = (const float*)d_in[2];
    const float* Whh  = (const float*)d_in[3];
    const float* bih  = (const float*)d_in[4];
    const float* bhh  = (const float*)d_in[5];
    const float* Wout = (const float*)d_in[6];
    const float* bout = (const float*)d_in[7];
    const float* W1   = (const float*)d_in[8];
    const float* b1   = (const float*)d_in[9];
    const float* W2   = (const float*)d_in[10];
    const float* b2   = (const float*)d_in[11];
    const float* W3   = (const float*)d_in[12];
    const float* b3   = (const float*)d_in[13];
    float* out = (float*)d_out;

    float *h, *acc, *gi, *gh;
    __nv_bfloat16 *A1, *z1b, *z2b, *xb, *W1b, *W2b, *W3b, *Wihb, *Whhb, *Woutb;
    cudaGetSymbolAddress((void**)&h, g_h);       cudaGetSymbolAddress((void**)&acc, g_acc);
    cudaGetSymbolAddress((void**)&gi, g_gi);     cudaGetSymbolAddress((void**)&gh, g_gh);
    cudaGetSymbolAddress((void**)&A1, g_A1);     cudaGetSymbolAddress((void**)&z1b, g_z1b);
    cudaGetSymbolAddress((void**)&z2b, g_z2b);   cudaGetSymbolAddress((void**)&xb, g_xb);
    cudaGetSymbolAddress((void**)&W1b, g_W1b);   cudaGetSymbolAddress((void**)&W2b, g_W2b);
    cudaGetSymbolAddress((void**)&W3b, g_W3b);   cudaGetSymbolAddress((void**)&Wihb, g_Wihb);
    cudaGetSymbolAddress((void**)&Whhb, g_Whhb); cudaGetSymbolAddress((void**)&Woutb, g_Woutb);

    // setup: convert weights/inputs, zero state
    zero_f<<<(BATCH * HID + 255) / 256, 256>>>(h, BATCH * HID);
    zero_bf<<<(BATCH * LDA1 + 255) / 256, 256>>>(A1, BATCH * LDA1);
    conv_w<<<(1024 * K1P + 255) / 256, 256>>>(W1, W1b, 1024, 513, K1P);
    conv_w<<<(1024 * 1024 + 255) / 256, 256>>>(W2, W2b, 1024, 1024, 1024);
    conv_w<<<(512 * 1024 + 255) / 256, 256>>>(W3, W3b, 512, 1024, 1024);
    conv_w<<<(1536 * 512 + 255) / 256, 256>>>(Wih, Wihb, 1536, 512, 512);
    conv_w<<<(1536 * K1P + 255) / 256, 256>>>(Whh, Whhb, 1536, 512, K1P);
    conv_w<<<(128 * K1P + 255) / 256, 256>>>(Wout, Woutb, 128, 512, K1P);
    conv_x<<<(BATCH * T_STEPS * 512 + 255) / 256, 256>>>(x, xb);

    const float amuls[4] = {0.f, 0.5f, 0.5f, 1.f};
    const float tcs  [4] = {0.f, 0.5f, 0.5f, 1.f};

    for (int step = 0; step < T_STEPS; step++) {
        if (step > 0) {  // step 0: dt==0 -> ODE is exactly identity, skip
            for (int rk = 0; rk < NSTEPS; rk++) {
                for (int ev = 0; ev < 4; ev++) {
                    // z1 = swish(A1 @ W1^T + b1); K_eff = 1728
                    GemmP p1 = {};
                    p1.A = A1; p1.W = W1b; p1.bias = b1; p1.K = LDA1;
                    p1.Cb = z1b; p1.ldcb = LDZ; p1.seg = 1024;
                    gemm_mma<1><<<dim3(16, 8), 128>>>(p1);

                    // z2 = swish(z1 @ W2^T + b2); K_eff = 3072
                    GemmP p2 = {};
                    p2.A = z1b; p2.W = W2b; p2.bias = b2; p2.K = LDZ;
                    p2.Cb = z2b; p2.ldcb = LDZ; p2.seg = 1024;
                    gemm_mma<1><<<dim3(16, 8), 128>>>(p2);

                    // k = z2 @ W3^T + b3; fused RK4 + next-A1 build; K_eff = 3072
                    GemmP p3 = {};
                    p3.A = z2b; p3.W = W3b; p3.bias = b3; p3.K = LDZ;
                    p3.ts = ts; p3.step = step;
                    p3.first = (ev == 0); p3.last = (ev == 3);
                    p3.kw = (ev == 1 || ev == 2) ? 2.f : 1.f;
                    p3.amul_next = (ev < 3) ? amuls[ev + 1] : 0.f;
                    p3.tc_next   = (ev < 3) ? ((float)rk + tcs[ev + 1]) : (float)(rk + 1);
                    p3.acc = acc; p3.h = h; p3.A1 = A1;
                    gemm_mma<2><<<dim3(8, 8), 128>>>(p3);
                }
            }
        }
        // GRU: gi = x_step @ Wih^T + bih (K_eff=1536); gh = h @ Whh^T + bhh (K_eff=1728)
        GemmP pg1 = {};
        pg1.A = xb + (size_t)step * BATCH * LDX; pg1.W = Wihb; pg1.bias = bih; pg1.K = LDX;
        pg1.Cf = gi; pg1.ldc = 1536;
        gemm_mma<0><<<dim3(24, 8), 128>>>(pg1);

        GemmP pg2 = {};
        pg2.A = A1; pg2.W = Whhb; pg2.bias = bhh; pg2.K = LDA1;
        pg2.Cf = gh; pg2.ldc = 1536;
        gemm_mma<0><<<dim3(24, 8), 128>>>(pg2);

        gru_gate<<<(BATCH * HID + 255) / 256, 256>>>(gi, gh, h, A1, ts, step);
    }

    // out = h @ Wout^T + bout (only last timestep's output); K_eff = 1728
    GemmP po = {};
    po.A = A1; po.W = Woutb; po.bias = bout; po.K = LDA1;
    po.Cf = out; po.ldc = 128;
    gemm_mma<0><<<dim3(2, 8), 128>>>(po);

    finalize_k<<<(BATCH * HID + 255) / 256, 256>>>(h, out);
}

// round 12
// speedup vs baseline: 2.2570x; 1.0554x over previous
#include <cuda_runtime.h>
#include <cuda_bf16.h>
#include <cstdint>

#define BATCH   512
#define T_STEPS 8
#define HID     512
#define LATD    64
#define NSTEPS  4
#define OUT_O   (BATCH * 2 * LATD)
#define OUT_H   (BATCH * HID)
#define K1P     576               // 513 padded to multiple of 64
#define LDA1    (3 * K1P)         // 1728: [hi | hi | lo]
#define LDZ     3072              // z buffers: [hi(1024) | hi(1024) | lo(1024)]
#define LDX     1536              // x: [hi(512) | hi(512) | lo(512)]

// ---------------- scratch (device globals) ----------------
__device__ float g_h  [BATCH * HID];
__device__ float g_acc[BATCH * HID];
__device__ float g_gi [T_STEPS * BATCH * 1536];   // all timesteps, batched
__device__ float g_gh [BATCH * 1536];
__device__ __nv_bfloat16 g_A1  [BATCH * LDA1];
__device__ __nv_bfloat16 g_z1b [BATCH * LDZ];
__device__ __nv_bfloat16 g_z2b [BATCH * LDZ];
__device__ __nv_bfloat16 g_xb  [T_STEPS * BATCH * LDX];
__device__ __nv_bfloat16 g_W1b [1024 * LDA1];
__device__ __nv_bfloat16 g_W2b [1024 * LDZ];
__device__ __nv_bfloat16 g_W3b [512 * LDZ];
__device__ __nv_bfloat16 g_Wihb[1536 * LDX];
__device__ __nv_bfloat16 g_Whhb[1536 * LDA1];
__device__ __nv_bfloat16 g_Woutb[128 * LDA1];

// ---------------- helpers ----------------
__device__ __forceinline__ uint32_t smem_u32(const void* p) {
    uint32_t a;
    asm("{ .reg .u64 t; cvta.to.shared.u64 t, %1; cvt.u32.u64 %0, t; }" : "=r"(a) : "l"(p));
    return a;
}
template<int N> __device__ __forceinline__ void cp_wait() {
    asm volatile("cp.async.wait_group %0;" :: "n"(N) : "memory");
}
__device__ __forceinline__ float sigm(float x) { return 1.f / (1.f + __expf(-x)); }
__device__ __forceinline__ __nv_bfloat162 pk2(__nv_bfloat16 a, __nv_bfloat16 b) {
    __nv_bfloat162 t; t.x = a; t.y = b; return t;
}

// ---------------- GEMM: C(MxN) = epi(A(MxK) @ W(NxK)^T + bias) ----------
// A rows: [hi|hi|lo] bf16, W rows: [hi|lo|hi] bf16 -> dot = hi*hi + hi*lo + lo*hi.
constexpr int SROW = 40;   // smem row stride (bf16): conflict-free ldmatrix phases

struct GemmP {
    const __nv_bfloat16* A;
    const __nv_bfloat16* W;
    const float* bias;
    int K;
    // EPI 0: f32 out
    float* Cf; int ldc;
    // EPI 1: bias+swish -> bf16 [hi|hi|lo]
    __nv_bfloat16* Cb; int ldcb; int seg;
    // EPI 2: RK4
    const float* ts; int step;
    float kw, amul_next, tc_next; int first, last;
    float* acc; float* h; __nv_bfloat16* A1;
};

// EPI: 0 = bias->f32, 1 = bias+swish->bf16 split, 2 = RK4 epilogue
// CTA tile: 64 x BN_, 8 warps (4 M-slices x 2 N-slices), warp tile 16 x BN_/2
template<int EPI, int BN_>
__global__ __launch_bounds__(256) void gemm_mma(GemmP p) {
    constexpr int NJ = BN_ / 16;          // n8 mma groups per warp (4 or 2)
    __shared__ __align__(16) __nv_bfloat16 sA[3][64 * SROW];
    __shared__ __align__(16) __nv_bfloat16 sB[3][BN_ * SROW];
    const int tid  = threadIdx.x;
    const int lane = tid & 31, wid = tid >> 5;
    const int wm = wid & 3, wn = wid >> 2;
    const int mBase = blockIdx.y * 64;
    const int nBase = blockIdx.x * BN_;
    const int KT = p.K >> 5;

    float ac[NJ][4];
#pragma unroll
    for (int j = 0; j < NJ; j++)
#pragma unroll
        for (int q = 0; q < 4; q++) ac[j][q] = 0.f;

    const int lr = tid >> 2;          // 0..63
    const int lc = (tid & 3) * 8;     // 0,8,16,24

    auto load_stage = [&](int s, int kt) {
        const __nv_bfloat16* Ag = p.A + (size_t)mBase * p.K + kt * 32;
        const __nv_bfloat16* Wg = p.W + (size_t)nBase * p.K + kt * 32;
        {
            const uint32_t da = smem_u32(&sA[s][0]) + (uint32_t)(lr * SROW + lc) * 2;
            const void* srca = (const void*)(Ag + (size_t)lr * p.K + lc);
            asm volatile("cp.async.cg.shared.global [%0], [%1], 16;" :: "r"(da), "l"(srca) : "memory");
        }
        if (lr < BN_) {
            const uint32_t db = smem_u32(&sB[s][0]) + (uint32_t)(lr * SROW + lc) * 2;
            const void* srcb = (const void*)(Wg + (size_t)lr * p.K + lc);
            asm volatile("cp.async.cg.shared.global [%0], [%1], 16;" :: "r"(db), "l"(srcb) : "memory");
        }
        asm volatile("cp.async.commit_group;" ::: "memory");
    };

    auto compute = [&](int s) {
        const uint32_t aB = smem_u32(&sA[s][0]);
        const uint32_t bB = smem_u32(&sB[s][0]);
#pragma unroll
        for (int kk = 0; kk < 32; kk += 16) {
            uint32_t af[4], bf[NJ][2];
            {
                const uint32_t ad = aB +
                    (uint32_t)(((wm * 16 + (lane & 15)) * SROW + kk + (lane >> 4) * 8) * 2);
                asm volatile("ldmatrix.sync.aligned.m8n8.x4.shared.b16 {%0,%1,%2,%3}, [%4];"
                    : "=r"(af[0]), "=r"(af[1]), "=r"(af[2]), "=r"(af[3]) : "r"(ad));
            }
#pragma unroll
            for (int jp = 0; jp < NJ / 2; jp++) {
                const int n = wn * (BN_ / 2) + jp * 16 + (lane >> 4) * 8 + (lane & 7);
                const int c = kk + ((lane >> 3) & 1) * 8;
                const uint32_t bd = bB + (uint32_t)((n * SROW + c) * 2);
                uint32_t r0, r1, r2, r3;
                asm volatile("ldmatrix.sync.aligned.m8n8.x4.shared.b16 {%0,%1,%2,%3}, [%4];"
                    : "=r"(r0), "=r"(r1), "=r"(r2), "=r"(r3) : "r"(bd));
                bf[jp * 2][0] = r0; bf[jp * 2][1] = r1;
                bf[jp * 2 + 1][0] = r2; bf[jp * 2 + 1][1] = r3;
            }
#pragma unroll
            for (int j = 0; j < NJ; j++)
                asm volatile(
                    "mma.sync.aligned.m16n8k16.row.col.f32.bf16.bf16.f32 "
                    "{%0,%1,%2,%3}, {%4,%5,%6,%7}, {%8,%9}, {%0,%1,%2,%3};"
                    : "+f"(ac[j][0]), "+f"(ac[j][1]), "+f"(ac[j][2]), "+f"(ac[j][3])
                    : "r"(af[0]), "r"(af[1]), "r"(af[2]), "r"(af[3]),
                      "r"(bf[j][0]), "r"(bf[j][1]));
        }
    };

    load_stage(0, 0);
    if (KT > 1) load_stage(1, 1);
    for (int kt = 0; kt < KT; kt++) {
        if (kt == KT - 1) cp_wait<0>(); else cp_wait<1>();
        __syncthreads();
        if (kt + 2 < KT) load_stage((kt + 2) % 3, kt + 2);
        compute(kt % 3);
    }

    // ---- epilogue ----
    const int rb = mBase + wm * 16 + (lane >> 2);
    const int cb = nBase + wn * (BN_ / 2) + (lane & 3) * 2;
#pragma unroll
    for (int rh = 0; rh < 2; rh++) {
        const int r = rb + rh * 8;
        float tpr = 0.f, dt = 0.f;
        if (EPI == 2) {
            tpr = p.ts[r * T_STEPS + p.step - 1];
            const float tcu = p.ts[r * T_STEPS + p.step];
            dt = (tcu - tpr) * 0.25f;
        }
#pragma unroll
        for (int j = 0; j < NJ; j++) {
            const int c = cb + j * 8;
            float v0 = ac[j][rh * 2 + 0] + p.bias[c];
            float v1 = ac[j][rh * 2 + 1] + p.bias[c + 1];
            if (EPI == 0) {
                float2 st = {v0, v1};
                *(float2*)(p.Cf + (size_t)r * p.ldc + c) = st;
            } else if (EPI == 1) {
                v0 = v0 * sigm(v0);
                v1 = v1 * sigm(v1);
                const __nv_bfloat16 h0 = __float2bfloat16_rn(v0);
                const __nv_bfloat16 h1 = __float2bfloat16_rn(v1);
                const __nv_bfloat162 hp = pk2(h0, h1);
                const __nv_bfloat162 lp =
                    pk2(__float2bfloat16_rn(v0 - __bfloat162float(h0)),
                        __float2bfloat16_rn(v1 - __bfloat162float(h1)));
                __nv_bfloat16* Ch = p.Cb + (size_t)r * p.ldcb + c;
                *(__nv_bfloat162*)Ch               = hp;
                *(__nv_bfloat162*)(Ch + p.seg)     = hp;
                *(__nv_bfloat162*)(Ch + 2 * p.seg) = lp;
            } else {  // EPI == 2
                const size_t idx = (size_t)r * HID + c;
                float a0, a1v;
                if (!p.last) {
                    const float av0 = p.first ? v0 : p.acc[idx]     + p.kw * v0;
                    const float av1 = p.first ? v1 : p.acc[idx + 1] + p.kw * v1;
                    p.acc[idx] = av0; p.acc[idx + 1] = av1;
                    a0  = p.h[idx]     + p.amul_next * dt * v0;
                    a1v = p.h[idx + 1] + p.amul_next * dt * v1;
                } else {
                    a0  = p.h[idx]     + dt * (1.f / 6.f) * (p.acc[idx]     + v0);
                    a1v = p.h[idx + 1] + dt * (1.f / 6.f) * (p.acc[idx + 1] + v1);
                    p.h[idx] = a0; p.h[idx + 1] = a1v;
                }
                const __nv_bfloat16 h0 = __float2bfloat16_rn(a0);
                const __nv_bfloat16 h1 = __float2bfloat16_rn(a1v);
                const __nv_bfloat162 hp = pk2(h0, h1);
                const __nv_bfloat162 lp =
                    pk2(__float2bfloat16_rn(a0 - __bfloat162float(h0)),
                        __float2bfloat16_rn(a1v - __bfloat162float(h1)));
                __nv_bfloat16* Ah = p.A1 + (size_t)r * LDA1 + c;
                *(__nv_bfloat162*)Ah             = hp;
                *(__nv_bfloat162*)(Ah + K1P)     = hp;
                *(__nv_bfloat162*)(Ah + 2 * K1P) = lp;
            }
        }
        if (EPI == 2 && nBase == 0 && wn == 0 && (lane & 3) == 0) {
            const float tn = tpr + p.tc_next * dt;
            const __nv_bfloat16 th = __float2bfloat16_rn(tn);
            const __nv_bfloat16 tl = __float2bfloat16_rn(tn - __bfloat162float(th));
            p.A1[(size_t)r * LDA1 + HID]           = th;
            p.A1[(size_t)r * LDA1 + K1P + HID]     = th;
            p.A1[(size_t)r * LDA1 + 2 * K1P + HID] = tl;
        }
    }
}

// ---------------- elementwise / setup kernels ----------------
__global__ void zero_f(float* p, int n) {
    int i = blockIdx.x * blockDim.x + threadIdx.x;
    if (i < n) p[i] = 0.f;
}
__global__ void zero_bf(__nv_bfloat16* p, int n) {
    int i = blockIdx.x * blockDim.x + threadIdx.x;
    if (i < n) p[i] = __float2bfloat16_rn(0.f);
}
// W[N][K] -> Wb[N][3*Kp] = [hi | lo | hi], zero-padded cols K..Kp-1
__global__ void conv_w(const float* __restrict__ W, __nv_bfloat16* __restrict__ Wb,
                       int N, int K, int Kp) {
    int idx = blockIdx.x * blockDim.x + threadIdx.x;
    if (idx >= N * Kp) return;
    const int n = idx / Kp, c = idx - n * Kp;
    const float v = (c < K) ? W[(size_t)n * K + c] : 0.f;
    const __nv_bfloat16 hi = __float2bfloat16_rn(v);
    const __nv_bfloat16 lo = __float2bfloat16_rn(v - __bfloat162float(hi));
    Wb[(size_t)n * 3 * Kp + c]          = hi;
    Wb[(size_t)n * 3 * Kp + Kp + c]     = lo;
    Wb[(size_t)n * 3 * Kp + 2 * Kp + c] = hi;
}
// x -> xb[step][r][1536] = [hi(512) | hi(512) | lo(512)]  (A-side layout)
__global__ void conv_x(const float* __restrict__ x, __nv_bfloat16* __restrict__ xb) {
    int idx = blockIdx.x * blockDim.x + threadIdx.x;   // idx = r*4096 + s*512 + c
    if (idx >= BATCH * T_STEPS * 512) return;
    const int c = idx & 511, s = (idx >> 9) & 7, r = idx >> 12;
    const float v = x[idx];
    const __nv_bfloat16 hi = __float2bfloat16_rn(v);
    __nv_bfloat16* dst = xb + ((size_t)s * BATCH + r) * LDX;
    dst[c]        = hi;
    dst[512 + c]  = hi;
    dst[1024 + c] = __float2bfloat16_rn(v - __bfloat162float(hi));
}
__global__ void gru_gate(const float* __restrict__ gi, const float* __restrict__ gh,
                         float* __restrict__ h, __nv_bfloat16* __restrict__ A1,
                         const float* __restrict__ ts, int step) {
    int idx = blockIdx.x * blockDim.x + threadIdx.x;
    if (idx >= BATCH * HID) return;
    const int r = idx >> 9, j = idx & 511;
    const float* gir = gi + (size_t)r * 1536;
    const float* ghr = gh + (size_t)r * 1536;
    const float rr = sigm(gir[j] + ghr[j]);
    const float zz = sigm(gir[512 + j] + ghr[512 + j]);
    const float nn = tanhf(gir[1024 + j] + rr * ghr[1024 + j]);
    const float hn = (1.f - zz) * nn + zz * h[idx];
    h[idx] = hn;
    const __nv_bfloat16 hi = __float2bfloat16_rn(hn);
    const __nv_bfloat16 lo = __float2bfloat16_rn(hn - __bfloat162float(hi));
    A1[(size_t)r * LDA1 + j]           = hi;
    A1[(size_t)r * LDA1 + K1P + j]     = hi;
    A1[(size_t)r * LDA1 + 2 * K1P + j] = lo;
    if (j == 0) {  // time column for next step: t_prev = ts[:, step]
        const float t = ts[r * T_STEPS + step];
        const __nv_bfloat16 th = __float2bfloat16_rn(t);
        const __nv_bfloat16 tl = __float2bfloat16_rn(t - __bfloat162float(th));
        A1[(size_t)r * LDA1 + HID]           = th;
        A1[(size_t)r * LDA1 + K1P + HID]     = th;
        A1[(size_t)r * LDA1 + 2 * K1P + HID] = tl;
    }
}
__global__ void finalize_k(const float* __restrict__ h, float* __restrict__ out) {
    int i = blockIdx.x * blockDim.x + threadIdx.x;
    if (i < BATCH * HID) {
        out[OUT_O + i]         = h[i];
        out[OUT_O + OUT_H + i] = 0.f;   // c never updated -> zeros
    }
}

// ---------------- host ----------------
extern "C" void kernel_launch(void* const* d_in, const int* in_sizes, int n_in,
                              void* d_out, int out_size) {
    const float* x    = (const float*)d_in[0];
    const float* ts   = (const float*)d_in[1];
    const float* Wih  = (const float*)d_in[2];
    const float* Whh  = (const float*)d_in[3];
    const float* bih  = (const float*)d_in[4];
    const float* bhh  = (const float*)d_in[5];
    const float* Wout = (const float*)d_in[6];
    const float* bout = (const float*)d_in[7];
    const float* W1   = (const float*)d_in[8];
    const float* b1   = (const float*)d_in[9];
    const float* W2   = (const float*)d_in[10];
    const float* b2   = (const float*)d_in[11];
    const float* W3   = (const float*)d_in[12];
    const float* b3   = (const float*)d_in[13];
    float* out = (float*)d_out;

    float *h, *acc, *gi, *gh;
    __nv_bfloat16 *A1, *z1b, *z2b, *xb, *W1b, *W2b, *W3b, *Wihb, *Whhb, *Woutb;
    cudaGetSymbolAddress((void**)&h, g_h);       cudaGetSymbolAddress((void**)&acc, g_acc);
    cudaGetSymbolAddress((void**)&gi, g_gi);     cudaGetSymbolAddress((void**)&gh, g_gh);
    cudaGetSymbolAddress((void**)&A1, g_A1);     cudaGetSymbolAddress((void**)&z1b, g_z1b);
    cudaGetSymbolAddress((void**)&z2b, g_z2b);   cudaGetSymbolAddress((void**)&xb, g_xb);
    cudaGetSymbolAddress((void**)&W1b, g_W1b);   cudaGetSymbolAddress((void**)&W2b, g_W2b);
    cudaGetSymbolAddress((void**)&W3b, g_W3b);   cudaGetSymbolAddress((void**)&Wihb, g_Wihb);
    cudaGetSymbolAddress((void**)&Whhb, g_Whhb); cudaGetSymbolAddress((void**)&Woutb, g_Woutb);

    // setup: convert weights/inputs, zero state
    zero_f<<<(BATCH * HID + 255) / 256, 256>>>(h, BATCH * HID);
    zero_bf<<<(BATCH * LDA1 + 255) / 256, 256>>>(A1, BATCH * LDA1);
    conv_w<<<(1024 * K1P + 255) / 256, 256>>>(W1, W1b, 1024, 513, K1P);
    conv_w<<<(1024 * 1024 + 255) / 256, 256>>>(W2, W2b, 1024, 1024, 1024);
    conv_w<<<(512 * 1024 + 255) / 256, 256>>>(W3, W3b, 512, 1024, 1024);
    conv_w<<<(1536 * 512 + 255) / 256, 256>>>(Wih, Wihb, 1536, 512, 512);
    conv_w<<<(1536 * K1P + 255) / 256, 256>>>(Whh, Whhb, 1536, 512, K1P);
    conv_w<<<(128 * K1P + 255) / 256, 256>>>(Wout, Woutb, 128, 512, K1P);
    conv_x<<<(BATCH * T_STEPS * 512 + 255) / 256, 256>>>(x, xb);

    // ALL timesteps' input-side GRU GEMM, batched: gi[s*512+r] = x_s @ Wih^T + bih
    {
        GemmP pg1 = {};
        pg1.A = xb; pg1.W = Wihb; pg1.bias = bih; pg1.K = LDX;
        pg1.Cf = gi; pg1.ldc = 1536;
        gemm_mma<0, 64><<<dim3(24, 64), 256>>>(pg1);   // M=4096, N=1536
    }

    const float amuls[4] = {0.f, 0.5f, 0.5f, 1.f};
    const float tcs  [4] = {0.f, 0.5f, 0.5f, 1.f};

    for (int step = 0; step < T_STEPS; step++) {
        if (step > 0) {  // step 0: dt==0 -> ODE is exactly identity, skip
            for (int rk = 0; rk < NSTEPS; rk++) {
                for (int ev = 0; ev < 4; ev++) {
                    // z1 = swish(A1 @ W1^T + b1); K_eff = 1728
                    GemmP p1 = {};
                    p1.A = A1; p1.W = W1b; p1.bias = b1; p1.K = LDA1;
                    p1.Cb = z1b; p1.ldcb = LDZ; p1.seg = 1024;
                    gemm_mma<1, 64><<<dim3(16, 8), 256>>>(p1);

                    // z2 = swish(z1 @ W2^T + b2); K_eff = 3072
                    GemmP p2 = {};
                    p2.A = z1b; p2.W = W2b; p2.bias = b2; p2.K = LDZ;
                    p2.Cb = z2b; p2.ldcb = LDZ; p2.seg = 1024;
                    gemm_mma<1, 64><<<dim3(16, 8), 256>>>(p2);

                    // k = z2 @ W3^T + b3; fused RK4 + next-A1 build; K_eff = 3072
                    GemmP p3 = {};
                    p3.A = z2b; p3.W = W3b; p3.bias = b3; p3.K = LDZ;
                    p3.ts = ts; p3.step = step;
                    p3.first = (ev == 0); p3.last = (ev == 3);
                    p3.kw = (ev == 1 || ev == 2) ? 2.f : 1.f;
                    p3.amul_next = (ev < 3) ? amuls[ev + 1] : 0.f;
                    p3.tc_next   = (ev < 3) ? ((float)rk + tcs[ev + 1]) : (float)(rk + 1);
                    p3.acc = acc; p3.h = h; p3.A1 = A1;
                    gemm_mma<2, 32><<<dim3(16, 8), 256>>>(p3);
                }
            }
        }
        // gh = h @ Whh^T + bhh (K_eff=1728)
        GemmP pg2 = {};
        pg2.A = A1; pg2.W = Whhb; pg2.bias = bhh; pg2.K = LDA1;
        pg2.Cf = gh; pg2.ldc = 1536;
        gemm_mma<0, 64><<<dim3(24, 8), 256>>>(pg2);

        gru_gate<<<(BATCH * HID + 255) / 256, 256>>>(
            gi + (size_t)step * BATCH * 1536, gh, h, A1, ts, step);
    }

    // out = h @ Wout^T + bout (only last timestep's output); K_eff = 1728
    GemmP po = {};
    po.A = A1; po.W = Woutb; po.bias = bout; po.K = LDA1;
    po.Cf = out; po.ldc = 128;
    gemm_mma<0, 64><<<dim3(2, 8), 256>>>(po);

    finalize_k<<<(BATCH * HID + 255) / 256, 256>>>(h, out);
}

// round 13
// speedup vs baseline: 3.8955x; 1.7260x over previous
#include <cuda_runtime.h>
#include <cuda_fp16.h>
#include <cstdint>

#define BATCH   512
#define T_STEPS 8
#define HID     512
#define LATD    64
#define NSTEPS  4
#define OUT_O   (BATCH * 2 * LATD)
#define OUT_H   (BATCH * HID)
#define KA1     576               // 513 padded to multiple of 64 (A1 physical K)
#define KE1     (2 * KA1)         // 1152 effective K for layer-1 (W1 = [hi|lo])
#define KAZ     1024              // z buffers physical K
#define KEZ     2048              // effective K for layers 2/3
#define KAX     512               // x physical K
#define KEX     1024              // effective K for Wih

// ---------------- scratch (device globals) ----------------
__device__ float g_h  [BATCH * HID];
__device__ float g_acc[BATCH * HID];
__device__ float g_gi [T_STEPS * BATCH * 1536];   // all timesteps, batched
__device__ float g_gh [BATCH * 1536];
__device__ __half g_A1  [BATCH * KA1];            // single fp16 activations
__device__ __half g_z1b [BATCH * KAZ];
__device__ __half g_z2b [BATCH * KAZ];
__device__ __half g_xb  [T_STEPS * BATCH * KAX];
__device__ __half g_W1b [1024 * KE1];             // [hi(576) | lo(576)]
__device__ __half g_W2b [1024 * KEZ];
__device__ __half g_W3b [512 * KEZ];
__device__ __half g_Wihb[1536 * KEX];
__device__ __half g_Whhb[1536 * KE1];
__device__ __half g_Woutb[128 * KE1];

// ---------------- helpers ----------------
__device__ __forceinline__ uint32_t smem_u32(const void* p) {
    uint32_t a;
    asm("{ .reg .u64 t; cvta.to.shared.u64 t, %1; cvt.u32.u64 %0, t; }" : "=r"(a) : "l"(p));
    return a;
}
template<int N> __device__ __forceinline__ void cp_wait() {
    asm volatile("cp.async.wait_group %0;" :: "n"(N) : "memory");
}
__device__ __forceinline__ float sigm(float x) { return 1.f / (1.f + __expf(-x)); }

// ---------------- GEMM: C(MxN) = epi(A(MxKa) @ W(NxK)^T + bias) ------------
// W rows: [hi | lo] fp16 exact split (K = 2*Ka). A rows: single fp16 (Ka wide);
// the K-loop wraps A's column offset for the second W segment, so
// dot = a*w_hi + a*w_lo = a*w exactly (w split is exact); only error is
// the single fp16 rounding of a (~2^-12 relative).
constexpr int SROW = 72;   // smem row stride (fp16): 64 + 8 pad, conflict-free ldmatrix
constexpr int BK   = 64;   // K per pipeline stage

struct GemmP {
    const __half* A; int Ka;       // physical A row stride / wrap point
    const __half* W; int K;        // effective K (= 2*Ka-ish, multiple of 64)
    const float* bias;
    // EPI 0: f32 out
    float* Cf; int ldc;
    // EPI 1: bias+swish -> fp16
    __half* Cb; int ldcb;
    // EPI 2: RK4
    const float* ts; int step;
    float kw, amul_next, tc_next; int first, last;
    float* acc; float* h; __half* A1;
};

// EPI: 0 = bias->f32, 1 = bias+swish->fp16, 2 = RK4 epilogue
// CTA tile: 64 x BN_, 8 warps (4 M x 2 N), warp tile 16 x BN_/2
template<int EPI, int BN_>
__global__ __launch_bounds__(256) void gemm_mma(GemmP p) {
    constexpr int NJ = BN_ / 16;              // n8 mma groups per warp (4 or 2)
    extern __shared__ __align__(16) char dsm[];
    __half* sAb = (__half*)dsm;                      // 3 stages x 64*SROW
    __half* sBb = sAb + 3 * 64 * SROW;               // 3 stages x BN_*SROW
    const int tid  = threadIdx.x;
    const int lane = tid & 31, wid = tid >> 5;
    const int wm = wid & 3, wn = wid >> 2;
    const int mBase = blockIdx.y * 64;
    const int nBase = blockIdx.x * BN_;
    const int KT = p.K / BK;

    float ac[NJ][4];
#pragma unroll
    for (int j = 0; j < NJ; j++)
#pragma unroll
        for (int q = 0; q < 4; q++) ac[j][q] = 0.f;

    const int lrow = tid >> 3;        // 0..31
    const int lcg  = (tid & 7) * 8;   // 0..56 step 8

    auto load_stage = [&](int s, int kt) {
        int aCol = kt * BK; if (aCol >= p.Ka) aCol -= p.Ka;   // wrap for 2nd W segment
        const __half* Ag = p.A + (size_t)mBase * p.Ka + aCol;
        const __half* Wg = p.W + (size_t)nBase * p.K + kt * BK;
        const uint32_t a0 = smem_u32(sAb + s * 64 * SROW);
        const uint32_t b0 = smem_u32(sBb + s * BN_ * SROW);
#pragma unroll
        for (int i = 0; i < 2; i++) {
            const int r = lrow + i * 32;
            const uint32_t d = a0 + (uint32_t)(r * SROW + lcg) * 2;
            const void* src = (const void*)(Ag + (size_t)r * p.Ka + lcg);
            asm volatile("cp.async.cg.shared.global [%0], [%1], 16;" :: "r"(d), "l"(src) : "memory");
        }
#pragma unroll
        for (int i = 0; i < (BN_ > 32 ? 2 : 1); i++) {
            const int r = lrow + i * 32;
            const uint32_t d = b0 + (uint32_t)(r * SROW + lcg) * 2;
            const void* src = (const void*)(Wg + (size_t)r * p.K + lcg);
            asm volatile("cp.async.cg.shared.global [%0], [%1], 16;" :: "r"(d), "l"(src) : "memory");
        }
        asm volatile("cp.async.commit_group;" ::: "memory");
    };

    auto compute = [&](int s) {
        const uint32_t aB = smem_u32(sAb + s * 64 * SROW);
        const uint32_t bB = smem_u32(sBb + s * BN_ * SROW);
#pragma unroll
        for (int kk = 0; kk < BK; kk += 16) {
            uint32_t af[4], bf[NJ][2];
            {
                const uint32_t ad = aB +
                    (uint32_t)(((wm * 16 + (lane & 15)) * SROW + kk + (lane >> 4) * 8) * 2);
                asm volatile("ldmatrix.sync.aligned.m8n8.x4.shared.b16 {%0,%1,%2,%3}, [%4];"
                    : "=r"(af[0]), "=r"(af[1]), "=r"(af[2]), "=r"(af[3]) : "r"(ad));
            }
#pragma unroll
            for (int jp = 0; jp < NJ / 2; jp++) {
                const int n = wn * (BN_ / 2) + jp * 16 + (lane >> 4) * 8 + (lane & 7);
                const int c = kk + ((lane >> 3) & 1) * 8;
                const uint32_t bd = bB + (uint32_t)((n * SROW + c) * 2);
                uint32_t r0, r1, r2, r3;
                asm volatile("ldmatrix.sync.aligned.m8n8.x4.shared.b16 {%0,%1,%2,%3}, [%4];"
                    : "=r"(r0), "=r"(r1), "=r"(r2), "=r"(r3) : "r"(bd));
                bf[jp * 2][0] = r0; bf[jp * 2][1] = r1;
                bf[jp * 2 + 1][0] = r2; bf[jp * 2 + 1][1] = r3;
            }
#pragma unroll
            for (int j = 0; j < NJ; j++)
                asm volatile(
                    "mma.sync.aligned.m16n8k16.row.col.f32.f16.f16.f32 "
                    "{%0,%1,%2,%3}, {%4,%5,%6,%7}, {%8,%9}, {%0,%1,%2,%3};"
                    : "+f"(ac[j][0]), "+f"(ac[j][1]), "+f"(ac[j][2]), "+f"(ac[j][3])
                    : "r"(af[0]), "r"(af[1]), "r"(af[2]), "r"(af[3]),
                      "r"(bf[j][0]), "r"(bf[j][1]));
        }
    };

    load_stage(0, 0);
    if (KT > 1) load_stage(1, 1);
    for (int kt = 0; kt < KT; kt++) {
        if (kt == KT - 1) cp_wait<0>(); else cp_wait<1>();
        __syncthreads();
        if (kt + 2 < KT) load_stage((kt + 2) % 3, kt + 2);
        compute(kt % 3);
    }

    // ---- epilogue ----
    const int rb = mBase + wm * 16 + (lane >> 2);
    const int cb = nBase + wn * (BN_ / 2) + (lane & 3) * 2;
#pragma unroll
    for (int rh = 0; rh < 2; rh++) {
        const int r = rb + rh * 8;
        float tpr = 0.f, dt = 0.f;
        if (EPI == 2) {
            tpr = p.ts[r * T_STEPS + p.step - 1];
            const float tcu = p.ts[r * T_STEPS + p.step];
            dt = (tcu - tpr) * 0.25f;
        }
#pragma unroll
        for (int j = 0; j < NJ; j++) {
            const int c = cb + j * 8;
            float v0 = ac[j][rh * 2 + 0] + p.bias[c];
            float v1 = ac[j][rh * 2 + 1] + p.bias[c + 1];
            if (EPI == 0) {
                float2 st = {v0, v1};
                *(float2*)(p.Cf + (size_t)r * p.ldc + c) = st;
            } else if (EPI == 1) {
                v0 = v0 * sigm(v0);
                v1 = v1 * sigm(v1);
                *(__half2*)(p.Cb + (size_t)r * p.ldcb + c) =
                    __floats2half2_rn(v0, v1);
            } else {  // EPI == 2: RK4
                const size_t idx = (size_t)r * HID + c;
                float a0, a1v;
                if (!p.last) {
                    const float av0 = p.first ? v0 : p.acc[idx]     + p.kw * v0;
                    const float av1 = p.first ? v1 : p.acc[idx + 1] + p.kw * v1;
                    p.acc[idx] = av0; p.acc[idx + 1] = av1;
                    a0  = p.h[idx]     + p.amul_next * dt * v0;
                    a1v = p.h[idx + 1] + p.amul_next * dt * v1;
                } else {
                    a0  = p.h[idx]     + dt * (1.f / 6.f) * (p.acc[idx]     + v0);
                    a1v = p.h[idx + 1] + dt * (1.f / 6.f) * (p.acc[idx + 1] + v1);
                    p.h[idx] = a0; p.h[idx + 1] = a1v;
                }
                *(__half2*)(p.A1 + (size_t)r * KA1 + c) = __floats2half2_rn(a0, a1v);
            }
        }
        if (EPI == 2 && nBase == 0 && wn == 0 && (lane & 3) == 0) {
            const float tn = tpr + p.tc_next * dt;
            p.A1[(size_t)r * KA1 + HID] = __float2half_rn(tn);
        }
    }
}

// ---------------- elementwise / setup kernels ----------------
__global__ void zero_f(float* p, int n) {
    int i = blockIdx.x * blockDim.x + threadIdx.x;
    if (i < n) p[i] = 0.f;
}
__global__ void zero_h(__half* p, int n) {
    int i = blockIdx.x * blockDim.x + threadIdx.x;
    if (i < n) p[i] = __float2half_rn(0.f);
}
// W[N][K] -> Wb[N][2*Kp] = [hi | lo] fp16 exact split, zero-padded cols K..Kp-1
__global__ void conv_w(const float* __restrict__ W, __half* __restrict__ Wb,
                       int N, int K, int Kp) {
    int idx = blockIdx.x * blockDim.x + threadIdx.x;
    if (idx >= N * Kp) return;
    const int n = idx / Kp, c = idx - n * Kp;
    const float v = (c < K) ? W[(size_t)n * K + c] : 0.f;
    const __half hi = __float2half_rn(v);
    Wb[(size_t)n * 2 * Kp + c]      = hi;
    Wb[(size_t)n * 2 * Kp + Kp + c] = __float2half_rn(v - __half2float(hi));
}
// x[r][s][c] -> xb[s][r][c] single fp16
__global__ void conv_x(const float* __restrict__ x, __half* __restrict__ xb) {
    int idx = blockIdx.x * blockDim.x + threadIdx.x;   // idx = r*4096 + s*512 + c
    if (idx >= BATCH * T_STEPS * KAX) return;
    const int c = idx & 511, s = (idx >> 9) & 7, r = idx >> 12;
    xb[((size_t)s * BATCH + r) * KAX + c] = __float2half_rn(x[idx]);
}
__global__ void gru_gate(const float* __restrict__ gi, const float* __restrict__ gh,
                         float* __restrict__ h, __half* __restrict__ A1,
                         const float* __restrict__ ts, int step) {
    int idx = blockIdx.x * blockDim.x + threadIdx.x;
    if (idx >= BATCH * HID) return;
    const int r = idx >> 9, j = idx & 511;
    const float* gir = gi + (size_t)r * 1536;
    const float* ghr = gh + (size_t)r * 1536;
    const float rr = sigm(gir[j] + ghr[j]);
    const float zz = sigm(gir[512 + j] + ghr[512 + j]);
    const float nn = tanhf(gir[1024 + j] + rr * ghr[1024 + j]);
    const float hn = (1.f - zz) * nn + zz * h[idx];
    h[idx] = hn;
    A1[(size_t)r * KA1 + j] = __float2half_rn(hn);
    if (j == 0) {  // time column for next step: t_prev = ts[:, step]
        A1[(size_t)r * KA1 + HID] = __float2half_rn(ts[r * T_STEPS + step]);
    }
}
__global__ void finalize_k(const float* __restrict__ h, float* __restrict__ out) {
    int i = blockIdx.x * blockDim.x + threadIdx.x;
    if (i < BATCH * HID) {
        out[OUT_O + i]         = h[i];
        out[OUT_O + OUT_H + i] = 0.f;   // c never updated -> zeros
    }
}

// ---------------- host ----------------
static inline int smem_for(int bn) { return (3 * 64 * SROW + 3 * bn * SROW) * 2; }

extern "C" void kernel_launch(void* const* d_in, const int* in_sizes, int n_in,
                              void* d_out, int out_size) {
    const float* x    = (const float*)d_in[0];
    const float* ts   = (const float*)d_in[1];
    const float* Wih  = (const float*)d_in[2];
    const float* Whh  = (const float*)d_in[3];
    const float* bih  = (const float*)d_in[4];
    const float* bhh  = (const float*)d_in[5];
    const float* Wout = (const float*)d_in[6];
    const float* bout = (const float*)d_in[7];
    const float* W1   = (const float*)d_in[8];
    const float* b1   = (const float*)d_in[9];
    const float* W2   = (const float*)d_in[10];
    const float* b2   = (const float*)d_in[11];
    const float* W3   = (const float*)d_in[12];
    const float* b3   = (const float*)d_in[13];
    float* out = (float*)d_out;

    float *h, *acc, *gi, *gh;
    __half *A1, *z1b, *z2b, *xb, *W1b, *W2b, *W3b, *Wihb, *Whhb, *Woutb;
    cudaGetSymbolAddress((void**)&h, g_h);       cudaGetSymbolAddress((void**)&acc, g_acc);
    cudaGetSymbolAddress((void**)&gi, g_gi);     cudaGetSymbolAddress((void**)&gh, g_gh);
    cudaGetSymbolAddress((void**)&A1, g_A1);     cudaGetSymbolAddress((void**)&z1b, g_z1b);
    cudaGetSymbolAddress((void**)&z2b, g_z2b);   cudaGetSymbolAddress((void**)&xb, g_xb);
    cudaGetSymbolAddress((void**)&W1b, g_W1b);   cudaGetSymbolAddress((void**)&W2b, g_W2b);
    cudaGetSymbolAddress((void**)&W3b, g_W3b);   cudaGetSymbolAddress((void**)&Wihb, g_Wihb);
    cudaGetSymbolAddress((void**)&Whhb, g_Whhb); cudaGetSymbolAddress((void**)&Woutb, g_Woutb);

    cudaFuncSetAttribute((const void*)gemm_mma<0, 64>,
                         cudaFuncAttributeMaxDynamicSharedMemorySize, smem_for(64));
    cudaFuncSetAttribute((const void*)gemm_mma<1, 64>,
                         cudaFuncAttributeMaxDynamicSharedMemorySize, smem_for(64));
    cudaFuncSetAttribute((const void*)gemm_mma<2, 32>,
                         cudaFuncAttributeMaxDynamicSharedMemorySize, smem_for(32));

    // setup: convert weights/inputs, zero state
    zero_f<<<(BATCH * HID + 255) / 256, 256>>>(h, BATCH * HID);
    zero_h<<<(BATCH * KA1 + 255) / 256, 256>>>(A1, BATCH * KA1);
    conv_w<<<(1024 * KA1 + 255) / 256, 256>>>(W1, W1b, 1024, 513, KA1);
    conv_w<<<(1024 * KAZ + 255) / 256, 256>>>(W2, W2b, 1024, 1024, KAZ);
    conv_w<<<(512 * KAZ + 255) / 256, 256>>>(W3, W3b, 512, 1024, KAZ);
    conv_w<<<(1536 * KAX + 255) / 256, 256>>>(Wih, Wihb, 1536, 512, KAX);
    conv_w<<<(1536 * KA1 + 255) / 256, 256>>>(Whh, Whhb, 1536, 512, KA1);
    conv_w<<<(128 * KA1 + 255) / 256, 256>>>(Wout, Woutb, 128, 512, KA1);
    conv_x<<<(BATCH * T_STEPS * KAX + 255) / 256, 256>>>(x, xb);

    // ALL timesteps' input-side GRU GEMM, batched: gi[s*512+r] = x_s @ Wih^T + bih
    {
        GemmP pg1 = {};
        pg1.A = xb; pg1.Ka = KAX; pg1.W = Wihb; pg1.K = KEX; pg1.bias = bih;
        pg1.Cf = gi; pg1.ldc = 1536;
        gemm_mma<0, 64><<<dim3(24, 64), 256, smem_for(64)>>>(pg1);   // M=4096, N=1536
    }

    const float amuls[4] = {0.f, 0.5f, 0.5f, 1.f};
    const float tcs  [4] = {0.f, 0.5f, 0.5f, 1.f};

    for (int step = 0; step < T_STEPS; step++) {
        if (step > 0) {  // step 0: dt==0 -> ODE is exactly identity, skip
            for (int rk = 0; rk < NSTEPS; rk++) {
                for (int ev = 0; ev < 4; ev++) {
                    // z1 = swish(A1 @ W1^T + b1); K_eff = 1152
                    GemmP p1 = {};
                    p1.A = A1; p1.Ka = KA1; p1.W = W1b; p1.K = KE1; p1.bias = b1;
                    p1.Cb = z1b; p1.ldcb = KAZ;
                    gemm_mma<1, 64><<<dim3(16, 8), 256, smem_for(64)>>>(p1);

                    // z2 = swish(z1 @ W2^T + b2); K_eff = 2048
                    GemmP p2 = {};
                    p2.A = z1b; p2.Ka = KAZ; p2.W = W2b; p2.K = KEZ; p2.bias = b2;
                    p2.Cb = z2b; p2.ldcb = KAZ;
                    gemm_mma<1, 64><<<dim3(16, 8), 256, smem_for(64)>>>(p2);

                    // k = z2 @ W3^T + b3; fused RK4 + next-A1 build; K_eff = 2048
                    GemmP p3 = {};
                    p3.A = z2b; p3.Ka = KAZ; p3.W = W3b; p3.K = KEZ; p3.bias = b3;
                    p3.ts = ts; p3.step = step;
                    p3.first = (ev == 0); p3.last = (ev == 3);
                    p3.kw = (ev == 1 || ev == 2) ? 2.f : 1.f;
                    p3.amul_next = (ev < 3) ? amuls[ev + 1] : 0.f;
                    p3.tc_next   = (ev < 3) ? ((float)rk + tcs[ev + 1]) : (float)(rk + 1);
                    p3.acc = acc; p3.h = h; p3.A1 = A1;
                    gemm_mma<2, 32><<<dim3(16, 8), 256, smem_for(32)>>>(p3);
                }
            }
        }
        // gh = h @ Whh^T + bhh; K_eff = 1152
        GemmP pg2 = {};
        pg2.A = A1; pg2.Ka = KA1; pg2.W = Whhb; pg2.K = KE1; pg2.bias = bhh;
        pg2.Cf = gh; pg2.ldc = 1536;
        gemm_mma<0, 64><<<dim3(24, 8), 256, smem_for(64)>>>(pg2);

        gru_gate<<<(BATCH * HID + 255) / 256, 256>>>(
            gi + (size_t)step * BATCH * 1536, gh, h, A1, ts, step);
    }

    // out = h @ Wout^T + bout (only last timestep's output); K_eff = 1152
    GemmP po = {};
    po.A = A1; po.Ka = KA1; po.W = Woutb; po.K = KE1; po.bias = bout;
    po.Cf = out; po.ldc = 128;
    gemm_mma<0, 64><<<dim3(2, 8), 256, smem_for(64)>>>(po);

    finalize_k<<<(BATCH * HID + 255) / 256, 256>>>(h, out);
}